// round 13
// baseline (speedup 1.0000x reference)
#include <cuda_runtime.h>
#include <cuda_fp16.h>

#define FULL_MASK 0xffffffffu

constexpr int FDIM = 512;
constexpr int KDIM = 128;
constexpr int MT   = 32;          // rows per CTA
constexpr int THREADS = 256;
constexpr float BN_EPS = 1e-3f;

// ---- scratch (device global: allocation-free) ----
__device__ __half g_Wh[(size_t)FDIM * KDIM];   // [f][k], k contiguous

// ---- smem layout (bytes) ----
// GEMM phase: A_hi [0,8K)  A_lo [8K,16K)  W buf0 [16K,32K)  W buf1 [32K,48K)
// epilogue:   zbuf [0, 32*516*4 = 66048) overlaps A/W
// always:     sS @66048 (2KB), sT @68096 (2KB)
// sparsemax:  cnt @70144 (128B), lists @70272 (32*256*4 = 32KB)
constexpr int SM_A_HI = 0;
constexpr int SM_A_LO = 8192;
constexpr int SM_W0   = 16384;
constexpr int SM_W1   = 32768;
constexpr int ZSTRIDE = 516;              // floats
constexpr int SM_SS   = 66048;
constexpr int SM_TT   = 68096;
constexpr int SM_CNT  = 70144;
constexpr int SM_LIST = 70272;
constexpr int CAP     = 256;              // active-list capacity per row
constexpr int SMEM_BYTES = SM_LIST + 32 * CAP * 4;   // 103040

// ---- PTX helpers (base ISA only) ----
__device__ __forceinline__ unsigned smem_u32(const void* p) {
    unsigned a;
    asm("{ .reg .u64 t; cvta.to.shared.u64 t, %1; cvt.u32.u64 %0, t; }" : "=r"(a) : "l"(p));
    return a;
}
__device__ __forceinline__ unsigned h2_bits(__half2 h) {
    return *(unsigned*)&h;
}
__device__ __forceinline__ void cpa16(unsigned dst, const void* src) {
    asm volatile("cp.async.cg.shared.global [%0], [%1], 16;" :: "r"(dst), "l"(src));
}
__device__ __forceinline__ void cp_commit() {
    asm volatile("cp.async.commit_group;" ::: "memory");
}
__device__ __forceinline__ void cp_wait0() {
    asm volatile("cp.async.wait_group 0;" ::: "memory");
}
__device__ __forceinline__ void ldsm4(unsigned* r, unsigned addr) {
    asm volatile("ldmatrix.sync.aligned.m8n8.x4.shared.b16 {%0,%1,%2,%3}, [%4];"
        : "=r"(r[0]), "=r"(r[1]), "=r"(r[2]), "=r"(r[3]) : "r"(addr));
}
__device__ __forceinline__ void ldsm2(unsigned* r, unsigned addr) {
    asm volatile("ldmatrix.sync.aligned.m8n8.x2.shared.b16 {%0,%1}, [%2];"
        : "=r"(r[0]), "=r"(r[1]) : "r"(addr));
}
__device__ __forceinline__ void mma16816(float* d, const unsigned* a, const unsigned* b) {
    asm volatile(
        "mma.sync.aligned.m16n8k16.row.col.f32.f16.f16.f32 "
        "{%0,%1,%2,%3},{%4,%5,%6,%7},{%8,%9},{%0,%1,%2,%3};"
        : "+f"(d[0]), "+f"(d[1]), "+f"(d[2]), "+f"(d[3])
        : "r"(a[0]), "r"(a[1]), "r"(a[2]), "r"(a[3]), "r"(b[0]), "r"(b[1]));
}

// ================= W conversion kernel =================
__global__ void conv_W_kernel(const float* __restrict__ W) {
    int idx = blockIdx.x * blockDim.x + threadIdx.x;   // 65536
    int k = idx >> 9;
    int f = idx & 511;
    g_Wh[(size_t)f * KDIM + k] = __float2half(W[(size_t)k * FDIM + f]);
}

// ================= main fused kernel =================
__global__ __launch_bounds__(THREADS, 2)
void attn_mma_kernel(const float* __restrict__ A,
                     const float* __restrict__ prior,
                     const float* __restrict__ bias,
                     const float* __restrict__ gamma,
                     const float* __restrict__ beta,
                     const float* __restrict__ mmean,
                     const float* __restrict__ mvar,
                     float* __restrict__ out) {
    extern __shared__ char sm[];
    const unsigned smb = smem_u32(sm);
    float* sS = (float*)(sm + SM_SS);
    float* sT = (float*)(sm + SM_TT);

    const int tid  = threadIdx.x;
    const int wid  = tid >> 5;     // 0..7 : n64 column slice
    const int lane = tid & 31;
    const int rowbase = blockIdx.x * MT;

    // BN constants (bias folded): z = dot*s + t
#pragma unroll
    for (int f = tid; f < FDIM; f += THREADS) {
        float s = gamma[f] * rsqrtf(mvar[f] + BN_EPS);
        sS[f] = s;
        sT[f] = (bias[f] - mmean[f]) * s + beta[f];
    }

    // ---- prologue: W chunk 0 via cp.async ----
#pragma unroll
    for (int p = 0; p < 4; p++) {          // 1024 x uint4
        int j = p * THREADS + tid;
        int n = j >> 1;
        int h = j & 1;
        const __half* src = g_Wh + (size_t)n * KDIM + 0 * 16 + h * 8;
        unsigned dst = smb + SM_W0
                     + n * 32 + ((h * 16) ^ (((n >> 2) & 1) << 4));
        cpa16(dst, src);
    }
    cp_commit();

    // ---- A fp32 -> fp16 hi/lo, converted in-kernel into swizzled smem ----
#pragma unroll
    for (int p = 0; p < 4; p++) {
        int j  = p * THREADS + tid;        // 0..1023  (32 rows x 32 float4)
        int r  = j >> 5;
        int k4 = j & 31;
        float4 v = ((const float4*)A)[(size_t)(rowbase + r) * 32 + k4];
        __half2 h01 = __floats2half2_rn(v.x, v.y);
        __half2 h23 = __floats2half2_rn(v.z, v.w);
        float2 hf01 = __half22float2(h01);
        float2 hf23 = __half22float2(h23);
        __half2 l01 = __floats2half2_rn(v.x - hf01.x, v.y - hf01.y);
        __half2 l23 = __floats2half2_rn(v.z - hf23.x, v.w - hf23.y);
        int chunk = k4 >> 1;               // 16B chunk index within row
        int sub   = (k4 & 1) * 8;          // 8B sub-offset
        unsigned off = (unsigned)(r * 256 + ((chunk * 16) ^ ((r & 7) << 4)) + sub);
        uint2 hv; hv.x = h2_bits(h01); hv.y = h2_bits(h23);
        uint2 lv; lv.x = h2_bits(l01); lv.y = h2_bits(l23);
        *(uint2*)(sm + SM_A_HI + off) = hv;
        *(uint2*)(sm + SM_A_LO + off) = lv;
    }

    float acc[2][8][4];
#pragma unroll
    for (int s = 0; s < 2; s++)
#pragma unroll
        for (int j = 0; j < 8; j++)
#pragma unroll
            for (int c = 0; c < 4; c++) acc[s][j][c] = 0.f;

    // ---- K loop: 8 chunks of 16, double-buffered W ----
#pragma unroll 1
    for (int kc = 0; kc < 8; kc++) {
        cp_wait0();
        __syncthreads();
        if (kc < 7) {
            const int base = ((kc + 1) & 1) ? SM_W1 : SM_W0;
#pragma unroll
            for (int p = 0; p < 4; p++) {
                int j = p * THREADS + tid;
                int n = j >> 1;
                int h = j & 1;
                const __half* src = g_Wh + (size_t)n * KDIM + (kc + 1) * 16 + h * 8;
                unsigned dst = smb + base
                             + n * 32 + ((h * 16) ^ (((n >> 2) & 1) << 4));
                cpa16(dst, src);
            }
            cp_commit();
        }
        const unsigned wb = smb + ((kc & 1) ? SM_W1 : SM_W0);

        // ---- load ALL fragments for this kc up front ----
        unsigned afrag[2][2][4];            // [sub m16][hi/lo]
        {
            int rr = lane & 15;
            int kk = kc * 16 + ((lane >> 4) << 3);
            unsigned sw = (unsigned)((kk * 2) ^ ((rr & 7) << 4));
#pragma unroll
            for (int sub = 0; sub < 2; sub++) {
                unsigned rb = (unsigned)((rr + sub * 16) * 256) + sw;
                ldsm4(afrag[sub][0], smb + SM_A_HI + rb);
                ldsm4(afrag[sub][1], smb + SM_A_LO + rb);
            }
        }
        unsigned bh[8][2];
        {
            const int bn = wid * 64 + (lane & 7);
            const unsigned bko = (lane & 8) ? 16u : 0u;
#pragma unroll
            for (int j = 0; j < 8; j++) {
                int n = bn + j * 8;
                unsigned sw = (unsigned)(n * 32) + (bko ^ (((n >> 2) & 1) << 4));
                ldsm2(bh[j], wb + sw);
            }
        }

        // ---- 2 passes x 16 independent MMAs ----
#pragma unroll
        for (int j = 0; j < 8; j++) {       // pass 1: ah * wh
            mma16816(acc[0][j], afrag[0][0], bh[j]);
            mma16816(acc[1][j], afrag[1][0], bh[j]);
        }
#pragma unroll
        for (int j = 0; j < 8; j++) {       // pass 2: al * wh
            mma16816(acc[0][j], afrag[0][1], bh[j]);
            mma16816(acc[1][j], afrag[1][1], bh[j]);
        }
    }
    __syncthreads();   // all MMA reads done; smem becomes zbuf

    // ---- write z = acc*s + t into zbuf (fragment layout scatter) ----
    float* zb = (float*)sm;
    {
        const int cbase = wid * 64 + (lane & 3) * 2;
        const int rbase = lane >> 2;
#pragma unroll
        for (int sub = 0; sub < 2; sub++) {
#pragma unroll
            for (int j = 0; j < 8; j++) {
                int c = cbase + j * 8;
                float2 sv = *(float2*)&sS[c];
                float2 tv = *(float2*)&sT[c];
                int r = rbase + sub * 16;
                float2 z0, z1;
                z0.x = fmaf(acc[sub][j][0], sv.x, tv.x);
                z0.y = fmaf(acc[sub][j][1], sv.y, tv.y);
                z1.x = fmaf(acc[sub][j][2], sv.x, tv.x);
                z1.y = fmaf(acc[sub][j][3], sv.y, tv.y);
                *(float2*)&zb[(size_t)r * ZSTRIDE + c] = z0;
                *(float2*)&zb[(size_t)(r + 8) * ZSTRIDE + c] = z1;
            }
        }
    }
    if (tid < 32) ((int*)(sm + SM_CNT))[tid] = 0;   // active-list counters
    __syncthreads();

    // ---- sparsemax: warp owns 4 rows, 16 vals/lane ----
    float v[4][16];
    const int lr0 = wid * 4;
#pragma unroll
    for (int r = 0; r < 4; r++) {
        size_t g = (size_t)(rowbase + lr0 + r);
#pragma unroll
        for (int sg = 0; sg < 4; sg++) {
            float4 b  = *(float4*)&zb[(size_t)(lr0 + r) * ZSTRIDE + sg * 128 + lane * 4];
            float4 pr = *(const float4*)&prior[g * FDIM + sg * 128 + lane * 4];
            v[r][sg * 4 + 0] = b.x * pr.x;
            v[r][sg * 4 + 1] = b.y * pr.y;
            v[r][sg * 4 + 2] = b.z * pr.z;
            v[r][sg * 4 + 3] = b.w * pr.w;
        }
    }

    float mx[4];
#pragma unroll
    for (int r = 0; r < 4; r++) {
        float m = v[r][0];
#pragma unroll
        for (int i = 1; i < 16; i++) m = fmaxf(m, v[r][i]);
        mx[r] = m;
    }
#pragma unroll
    for (int off = 16; off; off >>= 1)
#pragma unroll
        for (int r = 0; r < 4; r++)
            mx[r] = fmaxf(mx[r], __shfl_xor_sync(FULL_MASK, mx[r], off));

    // ---- compact active values (v > mx-1) into per-row smem lists ----
    // values <= mx-1 contribute exactly 0 to f(tau) for all tau in [mx-1, mx]
    int*   cnt   = (int*)(sm + SM_CNT);
    float* lists = (float*)(sm + SM_LIST);
#pragma unroll
    for (int r = 0; r < 4; r++) {
        const float thr = mx[r] - 1.0f;
        const int row = lr0 + r;
#pragma unroll
        for (int i = 0; i < 16; i++) {
            if (v[r][i] > thr) {
                int idx = atomicAdd(&cnt[row], 1);
                if (idx < CAP) lists[row * CAP + idx] = v[r][i];
            }
        }
    }
    __syncthreads();

    // emax = max padded word-groups over this warp's 4 rows (warp-uniform),
    // then pad EVERY row up to emax*32 so the scan never reads garbage.
    int cnts[4];
    int emax = 1;
#pragma unroll
    for (int r = 0; r < 4; r++) {
        int c = cnt[lr0 + r];
        if (c > CAP) c = CAP;
        cnts[r] = c;
        int e = (c + 31) >> 5;
        if (e > emax) emax = e;
    }
#pragma unroll
    for (int r = 0; r < 4; r++) {
        for (int p = cnts[r] + lane; p < emax * 32; p += 32)
            lists[(lr0 + r) * CAP + p] = -1e30f;
    }
    __syncwarp();

    // ---- bisection on tau over compacted lists ----
    float lo[4], hi[4];
#pragma unroll
    for (int r = 0; r < 4; r++) { lo[r] = mx[r] - 1.0f; hi[r] = mx[r]; }
#pragma unroll 1
    for (int it = 0; it < 17; ++it) {
        float mid[4], s4[4];
#pragma unroll
        for (int r = 0; r < 4; r++) { mid[r] = 0.5f * (lo[r] + hi[r]); s4[r] = 0.f; }
#pragma unroll 1
        for (int e = 0; e < emax; e++) {
#pragma unroll
            for (int r = 0; r < 4; r++) {
                float val = lists[(lr0 + r) * CAP + e * 32 + lane];
                s4[r] += fmaxf(val - mid[r], 0.f);
            }
        }
#pragma unroll
        for (int off = 16; off; off >>= 1)
#pragma unroll
            for (int r = 0; r < 4; r++)
                s4[r] += __shfl_xor_sync(FULL_MASK, s4[r], off);
#pragma unroll
        for (int r = 0; r < 4; r++) {
            if (s4[r] >= 1.0f) lo[r] = mid[r]; else hi[r] = mid[r];
        }
    }

#pragma unroll
    for (int r = 0; r < 4; r++) {
        const float tau = 0.5f * (lo[r] + hi[r]);
        size_t g = (size_t)(rowbase + lr0 + r);
#pragma unroll
        for (int sg = 0; sg < 4; sg++) {
            float4 o;
            o.x = fmaxf(v[r][sg * 4 + 0] - tau, 0.f);
            o.y = fmaxf(v[r][sg * 4 + 1] - tau, 0.f);
            o.z = fmaxf(v[r][sg * 4 + 2] - tau, 0.f);
            o.w = fmaxf(v[r][sg * 4 + 3] - tau, 0.f);
            *(float4*)&out[g * FDIM + sg * 128 + lane * 4] = o;
        }
    }
}

// ================= launch =================
extern "C" void kernel_launch(void* const* d_in, const int* in_sizes, int n_in,
                              void* d_out, int out_size) {
    const float* A     = (const float*)d_in[0];
    const float* prior = (const float*)d_in[1];
    const float* W     = (const float*)d_in[2];
    const float* bias  = (const float*)d_in[3];
    const float* gamma = (const float*)d_in[4];
    const float* beta  = (const float*)d_in[5];
    const float* mmean = (const float*)d_in[6];
    const float* mvar  = (const float*)d_in[7];
    float* out = (float*)d_out;

    const int B = in_sizes[1] / FDIM;          // prior is [B, 512]

    conv_W_kernel<<<128, 512>>>(W);

    cudaFuncSetAttribute(attn_mma_kernel,
                         cudaFuncAttributeMaxDynamicSharedMemorySize, SMEM_BYTES);
    attn_mma_kernel<<<B / MT, THREADS, SMEM_BYTES>>>(A, prior, bias, gamma, beta,
                                                     mmean, mvar, out);
}

// round 14
// speedup vs baseline: 1.2491x; 1.2491x over previous
#include <cuda_runtime.h>
#include <cuda_fp16.h>

#define FULL_MASK 0xffffffffu

constexpr int FDIM = 512;
constexpr int KDIM = 128;
constexpr int MT   = 32;          // rows per CTA
constexpr int THREADS = 256;
constexpr float BN_EPS = 1e-3f;

// ---- scratch (device global: allocation-free) ----
__device__ __half g_Wh[(size_t)FDIM * KDIM];   // [f][k], k contiguous

// ---- smem layout (bytes) ----
// GEMM phase: A_hi [0,8K)  A_lo [8K,16K)  W buf0 [16K,32K)  W buf1 [32K,48K)
// epilogue:   zbuf [0, 32*516*4 = 66048) overlaps A/W
// always:     sS @66048 (2KB), sT @68096 (2KB)
constexpr int SM_A_HI = 0;
constexpr int SM_A_LO = 8192;
constexpr int SM_W0   = 16384;
constexpr int SM_W1   = 32768;
constexpr int ZSTRIDE = 516;              // floats
constexpr int SM_SS   = 66048;
constexpr int SM_TT   = 68096;
constexpr int SMEM_BYTES = 70144;

// ---- PTX helpers (base ISA only) ----
__device__ __forceinline__ unsigned smem_u32(const void* p) {
    unsigned a;
    asm("{ .reg .u64 t; cvta.to.shared.u64 t, %1; cvt.u32.u64 %0, t; }" : "=r"(a) : "l"(p));
    return a;
}
__device__ __forceinline__ unsigned h2_bits(__half2 h) {
    return *(unsigned*)&h;
}
__device__ __forceinline__ void cpa16(unsigned dst, const void* src) {
    asm volatile("cp.async.cg.shared.global [%0], [%1], 16;" :: "r"(dst), "l"(src));
}
__device__ __forceinline__ void cp_commit() {
    asm volatile("cp.async.commit_group;" ::: "memory");
}
__device__ __forceinline__ void cp_wait0() {
    asm volatile("cp.async.wait_group 0;" ::: "memory");
}
__device__ __forceinline__ void ldsm4(unsigned* r, unsigned addr) {
    asm volatile("ldmatrix.sync.aligned.m8n8.x4.shared.b16 {%0,%1,%2,%3}, [%4];"
        : "=r"(r[0]), "=r"(r[1]), "=r"(r[2]), "=r"(r[3]) : "r"(addr));
}
__device__ __forceinline__ void ldsm2(unsigned* r, unsigned addr) {
    asm volatile("ldmatrix.sync.aligned.m8n8.x2.shared.b16 {%0,%1}, [%2];"
        : "=r"(r[0]), "=r"(r[1]) : "r"(addr));
}
__device__ __forceinline__ void mma16816(float* d, const unsigned* a, const unsigned* b) {
    asm volatile(
        "mma.sync.aligned.m16n8k16.row.col.f32.f16.f16.f32 "
        "{%0,%1,%2,%3},{%4,%5,%6,%7},{%8,%9},{%0,%1,%2,%3};"
        : "+f"(d[0]), "+f"(d[1]), "+f"(d[2]), "+f"(d[3])
        : "r"(a[0]), "r"(a[1]), "r"(a[2]), "r"(a[3]), "r"(b[0]), "r"(b[1]));
}

// ================= W conversion kernel =================
__global__ void conv_W_kernel(const float* __restrict__ W) {
    int idx = blockIdx.x * blockDim.x + threadIdx.x;   // 65536
    int k = idx >> 9;
    int f = idx & 511;
    g_Wh[(size_t)f * KDIM + k] = __float2half(W[(size_t)k * FDIM + f]);
}

// ================= main fused kernel =================
__global__ __launch_bounds__(THREADS, 2)
void attn_mma_kernel(const float* __restrict__ A,
                     const float* __restrict__ prior,
                     const float* __restrict__ bias,
                     const float* __restrict__ gamma,
                     const float* __restrict__ beta,
                     const float* __restrict__ mmean,
                     const float* __restrict__ mvar,
                     float* __restrict__ out) {
    extern __shared__ char sm[];
    const unsigned smb = smem_u32(sm);
    float* sS = (float*)(sm + SM_SS);
    float* sT = (float*)(sm + SM_TT);

    const int tid  = threadIdx.x;
    const int wid  = tid >> 5;     // 0..7 : n64 column slice
    const int lane = tid & 31;
    const int rowbase = blockIdx.x * MT;

    // BN constants (bias folded): z = dot*s + t
#pragma unroll
    for (int f = tid; f < FDIM; f += THREADS) {
        float s = gamma[f] * rsqrtf(mvar[f] + BN_EPS);
        sS[f] = s;
        sT[f] = (bias[f] - mmean[f]) * s + beta[f];
    }

    // ---- prologue: W chunk 0 via cp.async ----
#pragma unroll
    for (int p = 0; p < 4; p++) {          // 1024 x uint4
        int j = p * THREADS + tid;
        int n = j >> 1;
        int h = j & 1;
        const __half* src = g_Wh + (size_t)n * KDIM + 0 * 16 + h * 8;
        unsigned dst = smb + SM_W0
                     + n * 32 + ((h * 16) ^ (((n >> 2) & 1) << 4));
        cpa16(dst, src);
    }
    cp_commit();

    // ---- A fp32 -> fp16 hi/lo, converted in-kernel into swizzled smem ----
#pragma unroll
    for (int p = 0; p < 4; p++) {
        int j  = p * THREADS + tid;        // 0..1023  (32 rows x 32 float4)
        int r  = j >> 5;
        int k4 = j & 31;
        float4 v = ((const float4*)A)[(size_t)(rowbase + r) * 32 + k4];
        __half2 h01 = __floats2half2_rn(v.x, v.y);
        __half2 h23 = __floats2half2_rn(v.z, v.w);
        float2 hf01 = __half22float2(h01);
        float2 hf23 = __half22float2(h23);
        __half2 l01 = __floats2half2_rn(v.x - hf01.x, v.y - hf01.y);
        __half2 l23 = __floats2half2_rn(v.z - hf23.x, v.w - hf23.y);
        int chunk = k4 >> 1;               // 16B chunk index within row
        int sub   = (k4 & 1) * 8;          // 8B sub-offset
        unsigned off = (unsigned)(r * 256 + ((chunk * 16) ^ ((r & 7) << 4)) + sub);
        uint2 hv; hv.x = h2_bits(h01); hv.y = h2_bits(h23);
        uint2 lv; lv.x = h2_bits(l01); lv.y = h2_bits(l23);
        *(uint2*)(sm + SM_A_HI + off) = hv;
        *(uint2*)(sm + SM_A_LO + off) = lv;
    }

    float acc[2][8][4];
#pragma unroll
    for (int s = 0; s < 2; s++)
#pragma unroll
        for (int j = 0; j < 8; j++)
#pragma unroll
            for (int c = 0; c < 4; c++) acc[s][j][c] = 0.f;

    // ---- K loop: 8 chunks of 16, double-buffered W ----
#pragma unroll 1
    for (int kc = 0; kc < 8; kc++) {
        cp_wait0();
        __syncthreads();
        if (kc < 7) {
            const int base = ((kc + 1) & 1) ? SM_W1 : SM_W0;
#pragma unroll
            for (int p = 0; p < 4; p++) {
                int j = p * THREADS + tid;
                int n = j >> 1;
                int h = j & 1;
                const __half* src = g_Wh + (size_t)n * KDIM + (kc + 1) * 16 + h * 8;
                unsigned dst = smb + base
                             + n * 32 + ((h * 16) ^ (((n >> 2) & 1) << 4));
                cpa16(dst, src);
            }
            cp_commit();
        }
        const unsigned wb = smb + ((kc & 1) ? SM_W1 : SM_W0);

        // ---- load ALL fragments for this kc up front ----
        unsigned afrag[2][2][4];            // [sub m16][hi/lo]
        {
            int rr = lane & 15;
            int kk = kc * 16 + ((lane >> 4) << 3);
            unsigned sw = (unsigned)((kk * 2) ^ ((rr & 7) << 4));
#pragma unroll
            for (int sub = 0; sub < 2; sub++) {
                unsigned rb = (unsigned)((rr + sub * 16) * 256) + sw;
                ldsm4(afrag[sub][0], smb + SM_A_HI + rb);
                ldsm4(afrag[sub][1], smb + SM_A_LO + rb);
            }
        }
        unsigned bh[8][2];
        {
            const int bn = wid * 64 + (lane & 7);
            const unsigned bko = (lane & 8) ? 16u : 0u;
#pragma unroll
            for (int j = 0; j < 8; j++) {
                int n = bn + j * 8;
                unsigned sw = (unsigned)(n * 32) + (bko ^ (((n >> 2) & 1) << 4));
                ldsm2(bh[j], wb + sw);
            }
        }

        // ---- 2 passes x 16 independent MMAs ----
#pragma unroll
        for (int j = 0; j < 8; j++) {       // pass 1: ah * wh
            mma16816(acc[0][j], afrag[0][0], bh[j]);
            mma16816(acc[1][j], afrag[1][0], bh[j]);
        }
#pragma unroll
        for (int j = 0; j < 8; j++) {       // pass 2: al * wh
            mma16816(acc[0][j], afrag[0][1], bh[j]);
            mma16816(acc[1][j], afrag[1][1], bh[j]);
        }
    }
    __syncthreads();   // all MMA reads done; smem becomes zbuf

    // ---- write z = acc*s + t into zbuf (fragment layout scatter) ----
    float* zb = (float*)sm;
    {
        const int cbase = wid * 64 + (lane & 3) * 2;
        const int rbase = lane >> 2;
#pragma unroll
        for (int sub = 0; sub < 2; sub++) {
#pragma unroll
            for (int j = 0; j < 8; j++) {
                int c = cbase + j * 8;
                float2 sv = *(float2*)&sS[c];
                float2 tv = *(float2*)&sT[c];
                int r = rbase + sub * 16;
                float2 z0, z1;
                z0.x = fmaf(acc[sub][j][0], sv.x, tv.x);
                z0.y = fmaf(acc[sub][j][1], sv.y, tv.y);
                z1.x = fmaf(acc[sub][j][2], sv.x, tv.x);
                z1.y = fmaf(acc[sub][j][3], sv.y, tv.y);
                *(float2*)&zb[(size_t)r * ZSTRIDE + c] = z0;
                *(float2*)&zb[(size_t)(r + 8) * ZSTRIDE + c] = z1;
            }
        }
    }
    __syncthreads();

    // ---- sparsemax: warp owns 4 rows, 16 vals/lane ----
    float v[4][16];
    const int lr0 = wid * 4;
#pragma unroll
    for (int r = 0; r < 4; r++) {
        size_t g = (size_t)(rowbase + lr0 + r);
#pragma unroll
        for (int sg = 0; sg < 4; sg++) {
            float4 b  = *(float4*)&zb[(size_t)(lr0 + r) * ZSTRIDE + sg * 128 + lane * 4];
            float4 pr = *(const float4*)&prior[g * FDIM + sg * 128 + lane * 4];
            v[r][sg * 4 + 0] = b.x * pr.x;
            v[r][sg * 4 + 1] = b.y * pr.y;
            v[r][sg * 4 + 2] = b.z * pr.z;
            v[r][sg * 4 + 3] = b.w * pr.w;
        }
    }

    float mx[4];
#pragma unroll
    for (int r = 0; r < 4; r++) {
        float m = v[r][0];
#pragma unroll
        for (int i = 1; i < 16; i++) m = fmaxf(m, v[r][i]);
        mx[r] = m;
    }
#pragma unroll
    for (int off = 16; off; off >>= 1)
#pragma unroll
        for (int r = 0; r < 4; r++)
            mx[r] = fmaxf(mx[r], __shfl_xor_sync(FULL_MASK, mx[r], off));

    // ---- Michelot fixed-point: tau <- (sum_{v>tau} v - 1) / #{v>tau} ----
    // tau0 = mx-1 <= tau*; tau increases monotonically; at support fixpoint
    // this IS the reference formula (csum_k - 1)/k exactly.
    float tau[4];
#pragma unroll
    for (int r = 0; r < 4; r++) tau[r] = mx[r] - 1.0f;

#pragma unroll 1
    for (int it = 0; it < 7; ++it) {
        float s4[4], k4[4];
#pragma unroll
        for (int r = 0; r < 4; r++) { s4[r] = 0.f; k4[r] = 0.f; }
#pragma unroll
        for (int r = 0; r < 4; r++)
#pragma unroll
            for (int i = 0; i < 16; i++) {
                bool p = v[r][i] > tau[r];
                s4[r] += p ? v[r][i] : 0.f;
                k4[r] += p ? 1.f : 0.f;
            }
#pragma unroll
        for (int off = 16; off; off >>= 1)
#pragma unroll
            for (int r = 0; r < 4; r++) {
                s4[r] += __shfl_xor_sync(FULL_MASK, s4[r], off);
                k4[r] += __shfl_xor_sync(FULL_MASK, k4[r], off);
            }
#pragma unroll
        for (int r = 0; r < 4; r++)
            tau[r] = (s4[r] - 1.0f) / k4[r];
    }

#pragma unroll
    for (int r = 0; r < 4; r++) {
        size_t g = (size_t)(rowbase + lr0 + r);
#pragma unroll
        for (int sg = 0; sg < 4; sg++) {
            float4 o;
            o.x = fmaxf(v[r][sg * 4 + 0] - tau[r], 0.f);
            o.y = fmaxf(v[r][sg * 4 + 1] - tau[r], 0.f);
            o.z = fmaxf(v[r][sg * 4 + 2] - tau[r], 0.f);
            o.w = fmaxf(v[r][sg * 4 + 3] - tau[r], 0.f);
            *(float4*)&out[g * FDIM + sg * 128 + lane * 4] = o;
        }
    }
}

// ================= launch =================
extern "C" void kernel_launch(void* const* d_in, const int* in_sizes, int n_in,
                              void* d_out, int out_size) {
    const float* A     = (const float*)d_in[0];
    const float* prior = (const float*)d_in[1];
    const float* W     = (const float*)d_in[2];
    const float* bias  = (const float*)d_in[3];
    const float* gamma = (const float*)d_in[4];
    const float* beta  = (const float*)d_in[5];
    const float* mmean = (const float*)d_in[6];
    const float* mvar  = (const float*)d_in[7];
    float* out = (float*)d_out;

    const int B = in_sizes[1] / FDIM;          // prior is [B, 512]

    conv_W_kernel<<<128, 512>>>(W);

    cudaFuncSetAttribute(attn_mma_kernel,
                         cudaFuncAttributeMaxDynamicSharedMemorySize, SMEM_BYTES);
    attn_mma_kernel<<<B / MT, THREADS, SMEM_BYTES>>>(A, prior, bias, gamma, beta,
                                                     mmean, mvar, out);
}

// round 15
// speedup vs baseline: 1.4150x; 1.1328x over previous
#include <cuda_runtime.h>
#include <cuda_fp16.h>

#define FULL_MASK 0xffffffffu

constexpr int FDIM = 512;
constexpr int KDIM = 128;
constexpr int MT   = 32;          // rows per CTA
constexpr int THREADS = 256;
constexpr float BN_EPS = 1e-3f;

// ---- scratch (device global: allocation-free) ----
__device__ __half g_Wh[(size_t)FDIM * KDIM];   // [f][k], k contiguous

// ---- smem layout (bytes) ----
constexpr int SM_A_HI = 0;
constexpr int SM_A_LO = 8192;
constexpr int SM_W0   = 16384;
constexpr int SM_W1   = 32768;
constexpr int ZSTRIDE = 516;              // floats
constexpr int SM_SS   = 66048;
constexpr int SM_TT   = 68096;
constexpr int SMEM_BYTES = 70144;

// ---- PTX helpers (base ISA only) ----
__device__ __forceinline__ unsigned smem_u32(const void* p) {
    unsigned a;
    asm("{ .reg .u64 t; cvta.to.shared.u64 t, %1; cvt.u32.u64 %0, t; }" : "=r"(a) : "l"(p));
    return a;
}
__device__ __forceinline__ unsigned h2_bits(__half2 h) {
    return *(unsigned*)&h;
}
__device__ __forceinline__ void cpa16(unsigned dst, const void* src) {
    asm volatile("cp.async.cg.shared.global [%0], [%1], 16;" :: "r"(dst), "l"(src));
}
__device__ __forceinline__ void cp_commit() {
    asm volatile("cp.async.commit_group;" ::: "memory");
}
__device__ __forceinline__ void cp_wait0() {
    asm volatile("cp.async.wait_group 0;" ::: "memory");
}
__device__ __forceinline__ void ldsm4(unsigned* r, unsigned addr) {
    asm volatile("ldmatrix.sync.aligned.m8n8.x4.shared.b16 {%0,%1,%2,%3}, [%4];"
        : "=r"(r[0]), "=r"(r[1]), "=r"(r[2]), "=r"(r[3]) : "r"(addr));
}
__device__ __forceinline__ void ldsm2(unsigned* r, unsigned addr) {
    asm volatile("ldmatrix.sync.aligned.m8n8.x2.shared.b16 {%0,%1}, [%2];"
        : "=r"(r[0]), "=r"(r[1]) : "r"(addr));
}
__device__ __forceinline__ void mma16816(float* d, const unsigned* a, const unsigned* b) {
    asm volatile(
        "mma.sync.aligned.m16n8k16.row.col.f32.f16.f16.f32 "
        "{%0,%1,%2,%3},{%4,%5,%6,%7},{%8,%9},{%0,%1,%2,%3};"
        : "+f"(d[0]), "+f"(d[1]), "+f"(d[2]), "+f"(d[3])
        : "r"(a[0]), "r"(a[1]), "r"(a[2]), "r"(a[3]), "r"(b[0]), "r"(b[1]));
}
// predicated accumulate: if (v > tau) { s += v; k += 1.0f; }  (3 issue slots)
__device__ __forceinline__ void acc_if_gt(float& s, float& k, float v, float tau) {
    asm("{ .reg .pred p;\n\t"
        "setp.gt.f32 p, %2, %3;\n\t"
        "@p add.f32 %0, %0, %2;\n\t"
        "@p add.f32 %1, %1, 0f3F800000;\n\t}"
        : "+f"(s), "+f"(k) : "f"(v), "f"(tau));
}
__device__ __forceinline__ float fdiv_approx(float a, float b) {
    float r;
    asm("div.approx.f32 %0, %1, %2;" : "=f"(r) : "f"(a), "f"(b));
    return r;
}

// ================= W conversion kernel =================
__global__ void conv_W_kernel(const float* __restrict__ W) {
    int idx = blockIdx.x * blockDim.x + threadIdx.x;   // 65536
    int k = idx >> 9;
    int f = idx & 511;
    g_Wh[(size_t)f * KDIM + k] = __float2half(W[(size_t)k * FDIM + f]);
}

// ================= main fused kernel =================
__global__ __launch_bounds__(THREADS, 2)
void attn_mma_kernel(const float* __restrict__ A,
                     const float* __restrict__ prior,
                     const float* __restrict__ bias,
                     const float* __restrict__ gamma,
                     const float* __restrict__ beta,
                     const float* __restrict__ mmean,
                     const float* __restrict__ mvar,
                     float* __restrict__ out) {
    extern __shared__ char sm[];
    const unsigned smb = smem_u32(sm);
    float* sS = (float*)(sm + SM_SS);
    float* sT = (float*)(sm + SM_TT);

    const int tid  = threadIdx.x;
    const int wid  = tid >> 5;     // 0..7 : n64 column slice
    const int lane = tid & 31;
    const int rowbase = blockIdx.x * MT;

    // BN constants (bias folded): z = dot*s + t
#pragma unroll
    for (int f = tid; f < FDIM; f += THREADS) {
        float s = gamma[f] * rsqrtf(mvar[f] + BN_EPS);
        sS[f] = s;
        sT[f] = (bias[f] - mmean[f]) * s + beta[f];
    }

    // ---- prologue: W chunk 0 via cp.async ----
#pragma unroll
    for (int p = 0; p < 4; p++) {          // 1024 x uint4
        int j = p * THREADS + tid;
        int n = j >> 1;
        int h = j & 1;
        const __half* src = g_Wh + (size_t)n * KDIM + 0 * 16 + h * 8;
        unsigned dst = smb + SM_W0
                     + n * 32 + ((h * 16) ^ (((n >> 2) & 1) << 4));
        cpa16(dst, src);
    }
    cp_commit();

    // ---- A fp32 -> fp16 hi/lo, converted in-kernel into swizzled smem ----
#pragma unroll
    for (int p = 0; p < 4; p++) {
        int j  = p * THREADS + tid;        // 0..1023  (32 rows x 32 float4)
        int r  = j >> 5;
        int k4 = j & 31;
        float4 v = ((const float4*)A)[(size_t)(rowbase + r) * 32 + k4];
        __half2 h01 = __floats2half2_rn(v.x, v.y);
        __half2 h23 = __floats2half2_rn(v.z, v.w);
        float2 hf01 = __half22float2(h01);
        float2 hf23 = __half22float2(h23);
        __half2 l01 = __floats2half2_rn(v.x - hf01.x, v.y - hf01.y);
        __half2 l23 = __floats2half2_rn(v.z - hf23.x, v.w - hf23.y);
        int chunk = k4 >> 1;               // 16B chunk index within row
        int sub   = (k4 & 1) * 8;          // 8B sub-offset
        unsigned off = (unsigned)(r * 256 + ((chunk * 16) ^ ((r & 7) << 4)) + sub);
        uint2 hv; hv.x = h2_bits(h01); hv.y = h2_bits(h23);
        uint2 lv; lv.x = h2_bits(l01); lv.y = h2_bits(l23);
        *(uint2*)(sm + SM_A_HI + off) = hv;
        *(uint2*)(sm + SM_A_LO + off) = lv;
    }

    float acc[2][8][4];
#pragma unroll
    for (int s = 0; s < 2; s++)
#pragma unroll
        for (int j = 0; j < 8; j++)
#pragma unroll
            for (int c = 0; c < 4; c++) acc[s][j][c] = 0.f;

    // ---- K loop: 8 chunks of 16, double-buffered W ----
#pragma unroll 1
    for (int kc = 0; kc < 8; kc++) {
        cp_wait0();
        __syncthreads();
        if (kc < 7) {
            const int base = ((kc + 1) & 1) ? SM_W1 : SM_W0;
#pragma unroll
            for (int p = 0; p < 4; p++) {
                int j = p * THREADS + tid;
                int n = j >> 1;
                int h = j & 1;
                const __half* src = g_Wh + (size_t)n * KDIM + (kc + 1) * 16 + h * 8;
                unsigned dst = smb + base
                             + n * 32 + ((h * 16) ^ (((n >> 2) & 1) << 4));
                cpa16(dst, src);
            }
            cp_commit();
        }
        const unsigned wb = smb + ((kc & 1) ? SM_W1 : SM_W0);

        // ---- load ALL fragments for this kc up front ----
        unsigned afrag[2][2][4];            // [sub m16][hi/lo]
        {
            int rr = lane & 15;
            int kk = kc * 16 + ((lane >> 4) << 3);
            unsigned sw = (unsigned)((kk * 2) ^ ((rr & 7) << 4));
#pragma unroll
            for (int sub = 0; sub < 2; sub++) {
                unsigned rb = (unsigned)((rr + sub * 16) * 256) + sw;
                ldsm4(afrag[sub][0], smb + SM_A_HI + rb);
                ldsm4(afrag[sub][1], smb + SM_A_LO + rb);
            }
        }
        unsigned bh[8][2];
        {
            const int bn = wid * 64 + (lane & 7);
            const unsigned bko = (lane & 8) ? 16u : 0u;
#pragma unroll
            for (int j = 0; j < 8; j++) {
                int n = bn + j * 8;
                unsigned sw = (unsigned)(n * 32) + (bko ^ (((n >> 2) & 1) << 4));
                ldsm2(bh[j], wb + sw);
            }
        }

        // ---- 2 passes x 16 independent MMAs ----
#pragma unroll
        for (int j = 0; j < 8; j++) {       // pass 1: ah * wh
            mma16816(acc[0][j], afrag[0][0], bh[j]);
            mma16816(acc[1][j], afrag[1][0], bh[j]);
        }
#pragma unroll
        for (int j = 0; j < 8; j++) {       // pass 2: al * wh
            mma16816(acc[0][j], afrag[0][1], bh[j]);
            mma16816(acc[1][j], afrag[1][1], bh[j]);
        }
    }
    __syncthreads();   // all MMA reads done; smem becomes zbuf

    // ---- write z = acc*s + t into zbuf (fragment layout scatter) ----
    float* zb = (float*)sm;
    {
        const int cbase = wid * 64 + (lane & 3) * 2;
        const int rbase = lane >> 2;
#pragma unroll
        for (int sub = 0; sub < 2; sub++) {
#pragma unroll
            for (int j = 0; j < 8; j++) {
                int c = cbase + j * 8;
                float2 sv = *(float2*)&sS[c];
                float2 tv = *(float2*)&sT[c];
                int r = rbase + sub * 16;
                float2 z0, z1;
                z0.x = fmaf(acc[sub][j][0], sv.x, tv.x);
                z0.y = fmaf(acc[sub][j][1], sv.y, tv.y);
                z1.x = fmaf(acc[sub][j][2], sv.x, tv.x);
                z1.y = fmaf(acc[sub][j][3], sv.y, tv.y);
                *(float2*)&zb[(size_t)r * ZSTRIDE + c] = z0;
                *(float2*)&zb[(size_t)(r + 8) * ZSTRIDE + c] = z1;
            }
        }
    }
    __syncthreads();

    // ---- sparsemax: warp owns 4 rows, 16 vals/lane ----
    float v[4][16];
    const int lr0 = wid * 4;
#pragma unroll
    for (int r = 0; r < 4; r++) {
        size_t g = (size_t)(rowbase + lr0 + r);
#pragma unroll
        for (int sg = 0; sg < 4; sg++) {
            float4 b  = *(float4*)&zb[(size_t)(lr0 + r) * ZSTRIDE + sg * 128 + lane * 4];
            float4 pr = *(const float4*)&prior[g * FDIM + sg * 128 + lane * 4];
            v[r][sg * 4 + 0] = b.x * pr.x;
            v[r][sg * 4 + 1] = b.y * pr.y;
            v[r][sg * 4 + 2] = b.z * pr.z;
            v[r][sg * 4 + 3] = b.w * pr.w;
        }
    }

    float mx[4];
#pragma unroll
    for (int r = 0; r < 4; r++) {
        float m = v[r][0];
#pragma unroll
        for (int i = 1; i < 16; i++) m = fmaxf(m, v[r][i]);
        mx[r] = m;
    }
#pragma unroll
    for (int off = 16; off; off >>= 1)
#pragma unroll
        for (int r = 0; r < 4; r++)
            mx[r] = fmaxf(mx[r], __shfl_xor_sync(FULL_MASK, mx[r], off));

    // ---- Michelot fixed-point with early exit ----
    // tau <- (sum_{v>tau} v - 1) / #{v>tau}; tau0 = mx-1; monotone increasing.
    // Break when all 4 taus are bitwise stable (warp-uniform condition):
    // a stable tau is the exact fixpoint, further iters are identical.
    float tau[4];
#pragma unroll
    for (int r = 0; r < 4; r++) tau[r] = mx[r] - 1.0f;

#pragma unroll 1
    for (int it = 0; it < 8; ++it) {
        float s4[4], k4[4];
#pragma unroll
        for (int r = 0; r < 4; r++) { s4[r] = 0.f; k4[r] = 0.f; }
#pragma unroll
        for (int i = 0; i < 16; i++)
#pragma unroll
            for (int r = 0; r < 4; r++)
                acc_if_gt(s4[r], k4[r], v[r][i], tau[r]);
#pragma unroll
        for (int off = 16; off; off >>= 1)
#pragma unroll
            for (int r = 0; r < 4; r++) {
                s4[r] += __shfl_xor_sync(FULL_MASK, s4[r], off);
                k4[r] += __shfl_xor_sync(FULL_MASK, k4[r], off);
            }
        bool same = true;
#pragma unroll
        for (int r = 0; r < 4; r++) {
            float nt = fdiv_approx(s4[r] - 1.0f, k4[r]);
            same = same && (nt == tau[r]);
            tau[r] = nt;
        }
        if (same) break;   // s4,k4 warp-uniform -> 'same' warp-uniform
    }

#pragma unroll
    for (int r = 0; r < 4; r++) {
        size_t g = (size_t)(rowbase + lr0 + r);
#pragma unroll
        for (int sg = 0; sg < 4; sg++) {
            float4 o;
            o.x = fmaxf(v[r][sg * 4 + 0] - tau[r], 0.f);
            o.y = fmaxf(v[r][sg * 4 + 1] - tau[r], 0.f);
            o.z = fmaxf(v[r][sg * 4 + 2] - tau[r], 0.f);
            o.w = fmaxf(v[r][sg * 4 + 3] - tau[r], 0.f);
            *(float4*)&out[g * FDIM + sg * 128 + lane * 4] = o;
        }
    }
}

// ================= launch =================
extern "C" void kernel_launch(void* const* d_in, const int* in_sizes, int n_in,
                              void* d_out, int out_size) {
    const float* A     = (const float*)d_in[0];
    const float* prior = (const float*)d_in[1];
    const float* W     = (const float*)d_in[2];
    const float* bias  = (const float*)d_in[3];
    const float* gamma = (const float*)d_in[4];
    const float* beta  = (const float*)d_in[5];
    const float* mmean = (const float*)d_in[6];
    const float* mvar  = (const float*)d_in[7];
    float* out = (float*)d_out;

    const int B = in_sizes[1] / FDIM;          // prior is [B, 512]

    conv_W_kernel<<<128, 512>>>(W);

    cudaFuncSetAttribute(attn_mma_kernel,
                         cudaFuncAttributeMaxDynamicSharedMemorySize, SMEM_BYTES);
    attn_mma_kernel<<<B / MT, THREADS, SMEM_BYTES>>>(A, prior, bias, gamma, beta,
                                                     mmean, mvar, out);
}